// round 2
// baseline (speedup 1.0000x reference)
#include <cuda_runtime.h>
#include <cstdint>

#define Bq 128
#define Tq 512
#define TAGq 256
#define START_TAG 254
#define STOP_TAG 255
#define SROWS 192          // transT rows resident in SMEM
#define RSTRIDE 260        // floats per SMEM row (pad 4 -> conflict-free LDS.128)

// Scratch (allocation-free rule: static __device__ globals)
__device__ float g_hist[(size_t)Bq * Tq * TAGq];   // partition history, 64 MB
__device__ float g_transT[TAGq * TAGq];            // transposed transitions

__device__ __forceinline__ float2 fadd2_(float2 a, float2 b) {
    float2 o;
    asm("{\n\t"
        ".reg .b64 ra, rb, rc;\n\t"
        "mov.b64 ra, {%2,%3};\n\t"
        "mov.b64 rb, {%4,%5};\n\t"
        "add.rn.f32x2 rc, ra, rb;\n\t"
        "mov.b64 {%0,%1}, rc;\n\t"
        "}"
        : "=f"(o.x), "=f"(o.y)
        : "f"(a.x), "f"(a.y), "f"(b.x), "f"(b.y));
    return o;
}

__device__ __forceinline__ float neg_inf() { return __int_as_float(0xff800000u); }

// ---------------------------------------------------------------------------
// transT[t2][j] = trans[j][t2]
__global__ void transpose_kernel(const float* __restrict__ trans) {
    int j  = blockIdx.x;
    int t2 = threadIdx.x;
    g_transT[t2 * TAGq + j] = trans[j * TAGq + t2];
}

// ---------------------------------------------------------------------------
// Forward Viterbi: one CTA per batch, 256 threads (thread tid owns tag t2=tid).
// part_t stored to g_hist every step (argmax recomputed later along the path).
__global__ __launch_bounds__(256, 1)
void forward_kernel(const float* __restrict__ feats,
                    const float* __restrict__ trans) {
    extern __shared__ float smem_f[];
    float* tile  = smem_f;                       // [SROWS][RSTRIDE]
    float* partA = smem_f + SROWS * RSTRIDE;     // 256
    float* partB = partA + TAGq;                 // 256

    const int b = blockIdx.x, tid = threadIdx.x;

    // Stage transT rows [0, SROWS) into SMEM (vectorized, padded stride)
    for (int idx = tid; idx < SROWS * 64; idx += 256) {
        int r = idx >> 6, c4 = idx & 63;
        ((float4*)(tile + r * RSTRIDE))[c4] = ((const float4*)g_transT)[r * 64 + c4];
    }

    const float* febase = feats + (size_t)b * Tq * TAGq;
    float*       hbase  = g_hist + (size_t)b * Tq * TAGq;

    // part0 = feats[b,0,:] + trans[START,:]
    float p0 = febase[tid] + trans[START_TAG * TAGq + tid];
    partA[tid] = p0;
    hbase[tid] = p0;
    __syncthreads();

    const float4* myrow = (tid < SROWS)
        ? (const float4*)(tile + tid * RSTRIDE)
        : (const float4*)(g_transT + (size_t)tid * TAGq);

    float* cur = partA;
    float* nxt = partB;

    for (int t = 1; t < Tq; ++t) {
        const float e = __ldcs(febase + (size_t)t * TAGq + tid);
        const float2 e2 = make_float2(e, e);
        const float4* p4 = (const float4*)cur;

        float a0 = neg_inf(), a1 = a0, a2 = a0, a3 = a0;
        float a4 = a0, a5 = a0, a6 = a0, a7 = a0;

        #pragma unroll 8
        for (int k = 0; k < 64; k += 2) {
            float4 pa = p4[k], pb = p4[k + 1];
            float4 ta = myrow[k], tb = myrow[k + 1];
            float2 s;
            // exact reference order: (emit + trans) + part, round-to-nearest
            s = fadd2_(fadd2_(e2, make_float2(ta.x, ta.y)), make_float2(pa.x, pa.y));
            a0 = fmaxf(a0, s.x); a1 = fmaxf(a1, s.y);
            s = fadd2_(fadd2_(e2, make_float2(ta.z, ta.w)), make_float2(pa.z, pa.w));
            a2 = fmaxf(a2, s.x); a3 = fmaxf(a3, s.y);
            s = fadd2_(fadd2_(e2, make_float2(tb.x, tb.y)), make_float2(pb.x, pb.y));
            a4 = fmaxf(a4, s.x); a5 = fmaxf(a5, s.y);
            s = fadd2_(fadd2_(e2, make_float2(tb.z, tb.w)), make_float2(pb.z, pb.w));
            a6 = fmaxf(a6, s.x); a7 = fmaxf(a7, s.y);
        }
        float m = fmaxf(fmaxf(fmaxf(a0, a1), fmaxf(a2, a3)),
                        fmaxf(fmaxf(a4, a5), fmaxf(a6, a7)));
        nxt[tid] = m;
        hbase[(size_t)t * TAGq + tid] = m;
        __syncthreads();
        float* tp = cur; cur = nxt; nxt = tp;
    }
}

// ---------------------------------------------------------------------------
// Warp argmax with jnp.argmax semantics (first index of the max).
// Lane covers contiguous j = lane*8..lane*8+7; strict-greater ascending scan;
// cross-lane tie prefers smaller index.
__device__ __forceinline__ void warp_argmax_reduce(float& bv, int& bi) {
    #pragma unroll
    for (int o = 16; o; o >>= 1) {
        float ov = __shfl_down_sync(0xffffffffu, bv, o);
        int   oi = __shfl_down_sync(0xffffffffu, bi, o);
        if (ov > bv || (ov == bv && oi < bi)) { bv = ov; bi = oi; }
    }
    bv = __shfl_sync(0xffffffffu, bv, 0);
    bi = __shfl_sync(0xffffffffu, bi, 0);
}

// One warp per batch: final score + full backtrace with bp recomputation.
__global__ void backward_kernel(const float* __restrict__ feats,
                                const int*   __restrict__ mask,
                                float*       __restrict__ out) {
    const int b = blockIdx.x, lane = threadIdx.x;

    // lengths = sum(mask[b,:])
    int len = 0;
    for (int i = lane; i < Tq; i += 32) len += mask[b * Tq + i];
    #pragma unroll
    for (int o = 16; o; o >>= 1) len += __shfl_down_sync(0xffffffffu, len, o);
    len = __shfl_sync(0xffffffffu, len, 0);
    const int last = len - 1;

    const float* hb = g_hist + (size_t)b * Tq * TAGq;

    // path score / pointer: max_j last_part[j] + trans[j][STOP]
    {
        const float* lp = hb + (size_t)last * TAGq;
        const float* tc = g_transT + STOP_TAG * TAGq;
        float bv = neg_inf(); int bi = 0;
        #pragma unroll
        for (int k = 0; k < 8; ++k) {
            int j = lane * 8 + k;
            float v = lp[j] + tc[j];
            if (v > bv) { bv = v; bi = j; }
        }
        warp_argmax_reduce(bv, bi);
        if (lane == 0) out[b] = bv;

        float* dec = out + Bq;
        const int ptr = bi;
        if (lane == 0) dec[(size_t)b * Tq + (Tq - 1)] = (float)ptr;

        int cur = ptr;
        for (int i = Tq - 2; i >= 0; --i) {
            int nv;
            if (i == last) {
                nv = ptr;
            } else if (mask[b * Tq + i + 1] == 0) {
                nv = 0;
            } else {
                // recompute bp at time i+1, column cur — identical arithmetic
                // to the forward pass: (emit + trans) + part
                const float  e    = feats[((size_t)b * Tq + (i + 1)) * TAGq + cur];
                const float* hrow = hb + (size_t)i * TAGq;
                const float* trow = g_transT + (size_t)cur * TAGq;
                float xv = neg_inf(); int xi = 0;
                #pragma unroll
                for (int k = 0; k < 8; ++k) {
                    int j = lane * 8 + k;
                    float v = (e + trow[j]) + hrow[j];
                    if (v > xv) { xv = v; xi = j; }
                }
                warp_argmax_reduce(xv, xi);
                nv = xi;
            }
            cur = nv;
            if (lane == 0) dec[(size_t)b * Tq + i] = (float)cur;
        }
    }
}

// ---------------------------------------------------------------------------
extern "C" void kernel_launch(void* const* d_in, const int* in_sizes, int n_in,
                              void* d_out, int out_size) {
    const float* feats = (const float*)d_in[0];   // (128,512,256) f32
    const int*   mask  = (const int*)d_in[1];     // (128,512) i32
    const float* trans = (const float*)d_in[2];   // (256,256) f32
    float* out = (float*)d_out;                   // [128 path_score | 128*512 decode]

    transpose_kernel<<<TAGq, TAGq>>>(trans);

    const size_t smem = (size_t)(SROWS * RSTRIDE + 2 * TAGq) * sizeof(float); // 201728 B
    cudaFuncSetAttribute(forward_kernel,
                         cudaFuncAttributeMaxDynamicSharedMemorySize, (int)smem);
    forward_kernel<<<Bq, 256, smem>>>(feats, trans);

    backward_kernel<<<Bq, 32>>>(feats, mask, out);
}

// round 3
// speedup vs baseline: 1.0697x; 1.0697x over previous
#include <cuda_runtime.h>
#include <cstdint>

#define Bq 128
#define Tq 512
#define TAGq 256
#define START_TAG 254
#define STOP_TAG 255
#define SROWS 192          // transT rows resident in SMEM (multiple of 32!)
#define RSTRIDE 260        // floats per SMEM row (pad 4 -> conflict-free LDS.128)
#define NTHREADS 512       // 2-way j-split: tid = half*256 + t2

// Scratch (allocation-free rule: static __device__ globals)
__device__ float g_hist[(size_t)Bq * Tq * TAGq];   // partition history, 64 MB
__device__ float g_transT[TAGq * TAGq];            // transposed transitions

__device__ __forceinline__ float2 fadd2_(float2 a, float2 b) {
    float2 o;
    asm("{\n\t"
        ".reg .b64 ra, rb, rc;\n\t"
        "mov.b64 ra, {%2,%3};\n\t"
        "mov.b64 rb, {%4,%5};\n\t"
        "add.rn.f32x2 rc, ra, rb;\n\t"
        "mov.b64 {%0,%1}, rc;\n\t"
        "}"
        : "=f"(o.x), "=f"(o.y)
        : "f"(a.x), "f"(a.y), "f"(b.x), "f"(b.y));
    return o;
}

__device__ __forceinline__ float neg_inf() { return __int_as_float(0xff800000u); }

// max over 128 j-values: (e + trans[j]) + part[j], exact reference order.
// Kept as a separate inline per call site so each instantiation has a single,
// provable address space for t4 (SMEM vs GMEM) -> LDS.128 / LDG.128, not LD.E.
__device__ __forceinline__ float rowmax128(const float4* __restrict__ p4,
                                           const float4* __restrict__ t4,
                                           float2 e2) {
    float a0 = neg_inf(), a1 = a0, a2 = a0, a3 = a0;
    float a4 = a0, a5 = a0, a6 = a0, a7 = a0;
    #pragma unroll
    for (int k = 0; k < 32; k += 2) {
        float4 pa = p4[k], pb = p4[k + 1];
        float4 ta = t4[k], tb = t4[k + 1];
        float2 s;
        s = fadd2_(fadd2_(e2, make_float2(ta.x, ta.y)), make_float2(pa.x, pa.y));
        a0 = fmaxf(a0, s.x); a1 = fmaxf(a1, s.y);
        s = fadd2_(fadd2_(e2, make_float2(ta.z, ta.w)), make_float2(pa.z, pa.w));
        a2 = fmaxf(a2, s.x); a3 = fmaxf(a3, s.y);
        s = fadd2_(fadd2_(e2, make_float2(tb.x, tb.y)), make_float2(pb.x, pb.y));
        a4 = fmaxf(a4, s.x); a5 = fmaxf(a5, s.y);
        s = fadd2_(fadd2_(e2, make_float2(tb.z, tb.w)), make_float2(pb.z, pb.w));
        a6 = fmaxf(a6, s.x); a7 = fmaxf(a7, s.y);
    }
    return fmaxf(fmaxf(fmaxf(a0, a1), fmaxf(a2, a3)),
                 fmaxf(fmaxf(a4, a5), fmaxf(a6, a7)));
}

// ---------------------------------------------------------------------------
// transT[t2][j] = trans[j][t2]
__global__ void transpose_kernel(const float* __restrict__ trans) {
    int j  = blockIdx.x;
    int t2 = threadIdx.x;
    g_transT[t2 * TAGq + j] = trans[j * TAGq + t2];
}

// ---------------------------------------------------------------------------
// Forward Viterbi: one CTA per batch, 512 threads.
// Thread (half = tid>>8, t2 = tid&255) reduces j in [half*128, half*128+128).
__global__ __launch_bounds__(NTHREADS, 1)
void forward_kernel(const float* __restrict__ feats,
                    const float* __restrict__ trans) {
    extern __shared__ float smem_f[];
    float* tile    = smem_f;                        // [SROWS][RSTRIDE]
    float* partA   = smem_f + SROWS * RSTRIDE;      // 256
    float* partB   = partA + TAGq;                  // 256
    float* partial = partB + TAGq;                  // 512

    const int b   = blockIdx.x;
    const int tid = threadIdx.x;
    const int t2  = tid & 255;
    const int half = tid >> 8;

    // Stage transT rows [0, SROWS) into SMEM (vectorized, padded stride)
    for (int idx = tid; idx < SROWS * 64; idx += NTHREADS) {
        int r = idx >> 6, c4 = idx & 63;
        ((float4*)(tile + r * RSTRIDE))[c4] = ((const float4*)g_transT)[r * 64 + c4];
    }

    const float* febase = feats + (size_t)b * Tq * TAGq;
    float*       hbase  = g_hist + (size_t)b * Tq * TAGq;

    // part0 = feats[b,0,:] + trans[START,:]
    if (tid < TAGq) {
        float p0 = febase[tid] + trans[START_TAG * TAGq + tid];
        partA[tid] = p0;
        hbase[tid] = p0;
    }

    // prefetch emission for t = 1
    float e = __ldcs(febase + (size_t)TAGq + t2);
    __syncthreads();

    // per-thread trans row pointers (address-space-pure per branch below)
    const float4* trow_s = (const float4*)(tile + t2 * RSTRIDE) + half * 32;
    const float4* trow_g = (const float4*)(g_transT + (size_t)t2 * TAGq) + half * 32;

    float* cur = partA;
    float* nxt = partB;

    for (int t = 1; t < Tq; ++t) {
        // prefetch next step's emission (one full step of latency slack)
        const int tn = (t + 1 < Tq) ? (t + 1) : t;
        float e_nxt = __ldcs(febase + (size_t)tn * TAGq + t2);

        const float2 e2 = make_float2(e, e);
        const float4* p4 = (const float4*)cur + half * 32;

        float m;
        if (t2 < SROWS) m = rowmax128(p4, trow_s, e2);   // pure LDS path
        else            m = rowmax128(p4, trow_g, e2);   // pure LDG path

        partial[tid] = m;
        __syncthreads();

        if (tid < TAGq) {
            float mm = fmaxf(partial[tid], partial[tid + TAGq]);
            nxt[tid] = mm;
            hbase[(size_t)t * TAGq + tid] = mm;
        }
        __syncthreads();

        float* tp = cur; cur = nxt; nxt = tp;
        e = e_nxt;
    }
}

// ---------------------------------------------------------------------------
// Warp argmax with jnp.argmax semantics (first index of the max).
__device__ __forceinline__ void warp_argmax_reduce(float& bv, int& bi) {
    #pragma unroll
    for (int o = 16; o; o >>= 1) {
        float ov = __shfl_down_sync(0xffffffffu, bv, o);
        int   oi = __shfl_down_sync(0xffffffffu, bi, o);
        if (ov > bv || (ov == bv && oi < bi)) { bv = ov; bi = oi; }
    }
    bv = __shfl_sync(0xffffffffu, bv, 0);
    bi = __shfl_sync(0xffffffffu, bi, 0);
}

// One warp per batch: final score + full backtrace with bp recomputation.
__global__ void backward_kernel(const float* __restrict__ feats,
                                const int*   __restrict__ mask,
                                float*       __restrict__ out) {
    const int b = blockIdx.x, lane = threadIdx.x;

    int len = 0;
    for (int i = lane; i < Tq; i += 32) len += mask[b * Tq + i];
    #pragma unroll
    for (int o = 16; o; o >>= 1) len += __shfl_down_sync(0xffffffffu, len, o);
    len = __shfl_sync(0xffffffffu, len, 0);
    const int last = len - 1;

    const float* hb = g_hist + (size_t)b * Tq * TAGq;

    const float* lp = hb + (size_t)last * TAGq;
    const float* tc = g_transT + STOP_TAG * TAGq;
    float bv = neg_inf(); int bi = 0;
    #pragma unroll
    for (int k = 0; k < 8; ++k) {
        int j = lane * 8 + k;
        float v = lp[j] + tc[j];
        if (v > bv) { bv = v; bi = j; }
    }
    warp_argmax_reduce(bv, bi);
    if (lane == 0) out[b] = bv;

    float* dec = out + Bq;
    const int ptr = bi;
    if (lane == 0) dec[(size_t)b * Tq + (Tq - 1)] = (float)ptr;

    int cur = ptr;
    for (int i = Tq - 2; i >= 0; --i) {
        int nv;
        if (i == last) {
            nv = ptr;
        } else if (mask[b * Tq + i + 1] == 0) {
            nv = 0;
        } else {
            // recompute bp at time i+1, column cur — identical arithmetic
            const float  e    = feats[((size_t)b * Tq + (i + 1)) * TAGq + cur];
            const float* hrow = hb + (size_t)i * TAGq;
            const float* trow = g_transT + (size_t)cur * TAGq;
            float xv = neg_inf(); int xi = 0;
            #pragma unroll
            for (int k = 0; k < 8; ++k) {
                int j = lane * 8 + k;
                float v = (e + trow[j]) + hrow[j];
                if (v > xv) { xv = v; xi = j; }
            }
            warp_argmax_reduce(xv, xi);
            nv = xi;
        }
        cur = nv;
        if (lane == 0) dec[(size_t)b * Tq + i] = (float)cur;
    }
}

// ---------------------------------------------------------------------------
extern "C" void kernel_launch(void* const* d_in, const int* in_sizes, int n_in,
                              void* d_out, int out_size) {
    const float* feats = (const float*)d_in[0];   // (128,512,256) f32
    const int*   mask  = (const int*)d_in[1];     // (128,512) i32
    const float* trans = (const float*)d_in[2];   // (256,256) f32
    float* out = (float*)d_out;                   // [128 path_score | 128*512 decode]

    transpose_kernel<<<TAGq, TAGq>>>(trans);

    const size_t smem =
        (size_t)(SROWS * RSTRIDE + 2 * TAGq + NTHREADS) * sizeof(float); // 203776 B
    cudaFuncSetAttribute(forward_kernel,
                         cudaFuncAttributeMaxDynamicSharedMemorySize, (int)smem);
    forward_kernel<<<Bq, NTHREADS, smem>>>(feats, trans);

    backward_kernel<<<Bq, 32>>>(feats, mask, out);
}

// round 4
// speedup vs baseline: 2.4913x; 2.3289x over previous
#include <cuda_runtime.h>
#include <cstdint>

#define Bq 128
#define Tq 512
#define TAGq 256
#define START_TAG 254
#define STOP_TAG 255
#define NTHREADS 512       // 2-way j-split: tid = half*256 + t2
#define TCOLS 128          // SMEM tile cols per row (orig j in [64,128) U [192,256))
#define TSTRIDE 132        // floats per tile row = 33 float4 (odd -> conflict-free)

// Scratch (allocation-free rule: static __device__ globals)
__device__ float g_hist[(size_t)Bq * Tq * TAGq];   // partition history, 64 MB
__device__ float g_transT[TAGq * TAGq];            // transposed transitions

__device__ __forceinline__ float2 fadd2_(float2 a, float2 b) {
    float2 o;
    asm("{\n\t"
        ".reg .b64 ra, rb, rc;\n\t"
        "mov.b64 ra, {%2,%3};\n\t"
        "mov.b64 rb, {%4,%5};\n\t"
        "add.rn.f32x2 rc, ra, rb;\n\t"
        "mov.b64 {%0,%1}, rc;\n\t"
        "}"
        : "=f"(o.x), "=f"(o.y)
        : "f"(a.x), "f"(a.y), "f"(b.x), "f"(b.y));
    return o;
}

__device__ __forceinline__ float neg_inf() { return __int_as_float(0xff800000u); }

// ---------------------------------------------------------------------------
// transT[t2][j] = trans[j][t2]
__global__ void transpose_kernel(const float* __restrict__ trans) {
    int j  = blockIdx.x;
    int t2 = threadIdx.x;
    g_transT[t2 * TAGq + j] = trans[j * TAGq + t2];
}

// ---------------------------------------------------------------------------
// Forward Viterbi: one CTA per batch, 512 threads.
// Thread (half = tid>>8, t2 = tid&255) reduces j in [half*128, half*128+128).
// trans[j..j+64)   -> 16 float4 REGISTERS (loop-invariant, loaded once)
// trans[j+64..128) -> SMEM tile (compacted: 128 cols/row)
// part[]           -> SMEM, warp-broadcast loads
// NO LDG in the hot loop except the software-prefetched emission row.
__global__ __launch_bounds__(NTHREADS, 1)
void forward_kernel(const float* __restrict__ feats,
                    const float* __restrict__ trans) {
    extern __shared__ float smem_f[];
    float* tile    = smem_f;                        // [256][TSTRIDE]
    float* partA   = smem_f + TAGq * TSTRIDE;       // 256
    float* partB   = partA + TAGq;                  // 256
    float* partial = partB + TAGq;                  // 512

    const int b    = blockIdx.x;
    const int tid  = threadIdx.x;
    const int t2   = tid & 255;
    const int half = tid >> 8;

    // Stage compacted tile: tile[r][0:16) f4 = transT[r][16:32) f4 (orig cols 64..127)
    //                       tile[r][16:32) f4 = transT[r][48:64) f4 (orig cols 192..255)
    for (int idx = tid; idx < TAGq * 32; idx += NTHREADS) {
        int r = idx >> 5, c4 = idx & 31;
        int src4 = (c4 < 16) ? (c4 + 16) : (c4 + 32);
        ((float4*)(tile + r * TSTRIDE))[c4] =
            ((const float4*)g_transT)[r * 64 + src4];
    }

    // Register-resident trans slice: transT[t2][half*128 .. half*128+64)
    float4 tr4[16];
    {
        const float4* src = (const float4*)(g_transT + (size_t)t2 * TAGq) + half * 32;
        #pragma unroll
        for (int k = 0; k < 16; ++k) tr4[k] = src[k];
    }

    const float* febase = feats + (size_t)b * Tq * TAGq;
    float*       hbase  = g_hist + (size_t)b * Tq * TAGq;

    // part0 = feats[b,0,:] + trans[START,:]
    if (tid < TAGq) {
        float p0 = febase[tid] + trans[START_TAG * TAGq + tid];
        partA[tid] = p0;
        hbase[tid] = p0;
    }

    // prefetch emission for t = 1
    float e = __ldcs(febase + (size_t)TAGq + t2);
    __syncthreads();

    const float4* trow_s = (const float4*)(tile + t2 * TSTRIDE) + half * 16;

    float* cur = partA;
    float* nxt = partB;

    for (int t = 1; t < Tq; ++t) {
        // prefetch next step's emission (one full step of latency slack)
        const int tn = (t + 1 < Tq) ? (t + 1) : t;
        float e_nxt = __ldcs(febase + (size_t)tn * TAGq + t2);

        const float2 e2 = make_float2(e, e);
        const float4* p4 = (const float4*)cur + half * 32;  // warp-broadcast

        float a0 = neg_inf(), a1 = a0, a2 = a0, a3 = a0;
        float a4 = a0, a5 = a0, a6 = a0, a7 = a0;

        // j local [0,64): trans from registers
        #pragma unroll
        for (int k = 0; k < 16; ++k) {
            float4 pa = p4[k];
            float4 ta = tr4[k];
            float2 s;
            s = fadd2_(fadd2_(e2, make_float2(ta.x, ta.y)), make_float2(pa.x, pa.y));
            a0 = fmaxf(a0, s.x); a1 = fmaxf(a1, s.y);
            s = fadd2_(fadd2_(e2, make_float2(ta.z, ta.w)), make_float2(pa.z, pa.w));
            a2 = fmaxf(a2, s.x); a3 = fmaxf(a3, s.y);
        }
        // j local [64,128): trans from SMEM tile
        #pragma unroll
        for (int k = 0; k < 16; ++k) {
            float4 pb = p4[16 + k];
            float4 tb = trow_s[k];
            float2 s;
            s = fadd2_(fadd2_(e2, make_float2(tb.x, tb.y)), make_float2(pb.x, pb.y));
            a4 = fmaxf(a4, s.x); a5 = fmaxf(a5, s.y);
            s = fadd2_(fadd2_(e2, make_float2(tb.z, tb.w)), make_float2(pb.z, pb.w));
            a6 = fmaxf(a6, s.x); a7 = fmaxf(a7, s.y);
        }
        float m = fmaxf(fmaxf(fmaxf(a0, a1), fmaxf(a2, a3)),
                        fmaxf(fmaxf(a4, a5), fmaxf(a6, a7)));

        partial[tid] = m;
        __syncthreads();

        if (tid < TAGq) {
            float mm = fmaxf(partial[tid], partial[tid + TAGq]);
            nxt[tid] = mm;
            hbase[(size_t)t * TAGq + tid] = mm;
        }
        __syncthreads();

        float* tp = cur; cur = nxt; nxt = tp;
        e = e_nxt;
    }
}

// ---------------------------------------------------------------------------
// Warp argmax with jnp.argmax semantics (first index of the max).
__device__ __forceinline__ void warp_argmax_reduce(float& bv, int& bi) {
    #pragma unroll
    for (int o = 16; o; o >>= 1) {
        float ov = __shfl_down_sync(0xffffffffu, bv, o);
        int   oi = __shfl_down_sync(0xffffffffu, bi, o);
        if (ov > bv || (ov == bv && oi < bi)) { bv = ov; bi = oi; }
    }
    bv = __shfl_sync(0xffffffffu, bv, 0);
    bi = __shfl_sync(0xffffffffu, bi, 0);
}

// One warp per batch: final score + full backtrace with bp recomputation.
__global__ void backward_kernel(const float* __restrict__ feats,
                                const int*   __restrict__ mask,
                                float*       __restrict__ out) {
    const int b = blockIdx.x, lane = threadIdx.x;

    int len = 0;
    for (int i = lane; i < Tq; i += 32) len += mask[b * Tq + i];
    #pragma unroll
    for (int o = 16; o; o >>= 1) len += __shfl_down_sync(0xffffffffu, len, o);
    len = __shfl_sync(0xffffffffu, len, 0);
    const int last = len - 1;

    const float* hb = g_hist + (size_t)b * Tq * TAGq;

    const float* lp = hb + (size_t)last * TAGq;
    const float* tc = g_transT + STOP_TAG * TAGq;
    float bv = neg_inf(); int bi = 0;
    #pragma unroll
    for (int k = 0; k < 8; ++k) {
        int j = lane * 8 + k;
        float v = lp[j] + tc[j];
        if (v > bv) { bv = v; bi = j; }
    }
    warp_argmax_reduce(bv, bi);
    if (lane == 0) out[b] = bv;

    float* dec = out + Bq;
    const int ptr = bi;
    if (lane == 0) dec[(size_t)b * Tq + (Tq - 1)] = (float)ptr;

    int cur = ptr;
    for (int i = Tq - 2; i >= 0; --i) {
        int nv;
        if (i == last) {
            nv = ptr;
        } else if (mask[b * Tq + i + 1] == 0) {
            nv = 0;
        } else {
            // recompute bp at time i+1, column cur — identical arithmetic
            const float  e    = feats[((size_t)b * Tq + (i + 1)) * TAGq + cur];
            const float* hrow = hb + (size_t)i * TAGq;
            const float* trow = g_transT + (size_t)cur * TAGq;
            float xv = neg_inf(); int xi = 0;
            #pragma unroll
            for (int k = 0; k < 8; ++k) {
                int j = lane * 8 + k;
                float v = (e + trow[j]) + hrow[j];
                if (v > xv) { xv = v; xi = j; }
            }
            warp_argmax_reduce(xv, xi);
            nv = xi;
        }
        cur = nv;
        if (lane == 0) dec[(size_t)b * Tq + i] = (float)cur;
    }
}

// ---------------------------------------------------------------------------
extern "C" void kernel_launch(void* const* d_in, const int* in_sizes, int n_in,
                              void* d_out, int out_size) {
    const float* feats = (const float*)d_in[0];   // (128,512,256) f32
    const int*   mask  = (const int*)d_in[1];     // (128,512) i32
    const float* trans = (const float*)d_in[2];   // (256,256) f32
    float* out = (float*)d_out;                   // [128 path_score | 128*512 decode]

    transpose_kernel<<<TAGq, TAGq>>>(trans);

    const size_t smem =
        (size_t)(TAGq * TSTRIDE + 2 * TAGq + NTHREADS) * sizeof(float); // 139264 B
    cudaFuncSetAttribute(forward_kernel,
                         cudaFuncAttributeMaxDynamicSharedMemorySize, (int)smem);
    forward_kernel<<<Bq, NTHREADS, smem>>>(feats, trans);

    backward_kernel<<<Bq, 32>>>(feats, mask, out);
}